// round 15
// baseline (speedup 1.0000x reference)
#include <cuda_runtime.h>
#include <cuda_fp16.h>
#include <cstdint>

// Problem constants
#define MTOT 16384      // 2 streams * B(4) * L(2048)
#define HALF_M 8192
#define DIM 512
#define PF 2048
#define QKVN 1536
#define NB 4
#define NH 8
#define DH 64
#define LN_EPS 1e-5f
#define NSLICE 16

// ---------------- scratch (static device globals; no allocation) -------------
__device__ __half g_Xh   [MTOT * DIM];    // fp16 stacked input (GEMM operand)
__device__ __half g_QKVh [MTOT * QKVN];   // fused QKV output (fp16) [Q|K|V]
__device__ __half g_attnh[MTOT * DIM];    // fp16 attn (Wo operand)
__device__ float  g_proj [MTOT * DIM];
__device__ float  g_x1   [MTOT * DIM];    // exact (LN2 residual)
__device__ __half g_x1h  [MTOT * DIM];    // fp16 (FF1 operand)
__device__ __half g_h1h  [MTOT * PF];     // fp16 FF intermediate
__device__ float  g_ff   [MTOT * DIM];
__device__ float  g_Spart[NSLICE * NB * NH * DH * DH];
__device__ __half g_Shi  [NB * NH * DH * DH];   // S^T hi (fp16), layout [bh][d][e]
__device__ __half g_Slo  [NB * NH * DH * DH];   // S^T lo residual (fp16)
// packed fp16 weights + fp32 bias
__device__ __half g_Wqkvh[QKVN * DIM];
__device__ float  g_bqkv [QKVN];
__device__ __half g_Woh  [DIM * DIM];
__device__ __half g_W1h  [PF * DIM];
__device__ __half g_W2h  [DIM * PF];

// ---------------- helpers ----------------------------------------------------
__device__ __forceinline__ uint32_t smem_u32(const void* p) {
    uint32_t a;
    asm("{ .reg .u64 t; cvta.to.shared.u64 t, %1; cvt.u32.u64 %0, t; }" : "=r"(a) : "l"(p));
    return a;
}
__device__ __forceinline__ void mma_f16(float& c0, float& c1, float& c2, float& c3,
                                        uint32_t a0, uint32_t a1, uint32_t a2, uint32_t a3,
                                        uint32_t b0, uint32_t b1)
{
    asm volatile(
        "mma.sync.aligned.m16n8k16.row.col.f32.f16.f16.f32 "
        "{%0,%1,%2,%3}, {%4,%5,%6,%7}, {%8,%9}, {%0,%1,%2,%3};"
        : "+f"(c0), "+f"(c1), "+f"(c2), "+f"(c3)
        : "r"(a0), "r"(a1), "r"(a2), "r"(a3), "r"(b0), "r"(b1));
}
__device__ __forceinline__ void ldsm4(uint32_t& r0, uint32_t& r1, uint32_t& r2, uint32_t& r3,
                                      uint32_t addr)
{
    asm volatile("ldmatrix.sync.aligned.m8n8.x4.shared.b16 {%0,%1,%2,%3}, [%4];"
                 : "=r"(r0), "=r"(r1), "=r"(r2), "=r"(r3) : "r"(addr));
}
__device__ __forceinline__ void ldsm4t(uint32_t& r0, uint32_t& r1, uint32_t& r2, uint32_t& r3,
                                       uint32_t addr)
{
    asm volatile("ldmatrix.sync.aligned.m8n8.x4.trans.shared.b16 {%0,%1,%2,%3}, [%4];"
                 : "=r"(r0), "=r"(r1), "=r"(r2), "=r"(r3) : "r"(addr));
}
__device__ __forceinline__ void cp16(uint32_t saddr, const void* g) {
    asm volatile("cp.async.cg.shared.global [%0], [%1], 16;" :: "r"(saddr), "l"(g) : "memory");
}
__device__ __forceinline__ void h4store(__half* dst, float4 v) {
    __half2* d = reinterpret_cast<__half2*>(dst);
    d[0] = __floats2half2_rn(v.x, v.y);
    d[1] = __floats2half2_rn(v.z, v.w);
}

// ---------------- fused prep + pack (one launch) -------------------------------
#define PACK_N4 (HALF_M * DIM / 4)   // 1048576
__global__ void prep_pack_kernel(const float* __restrict__ qa, const float* __restrict__ qb,
                                 const float* __restrict__ Wq, const float* __restrict__ Wk,
                                 const float* __restrict__ Wv, const float* __restrict__ Wo,
                                 const float* __restrict__ W1, const float* __restrict__ W2,
                                 const float* __restrict__ bq, const float* __restrict__ bk,
                                 const float* __restrict__ bv)
{
    int i = blockIdx.x * blockDim.x + threadIdx.x;
    if (i < PACK_N4) {
        h4store(&g_Xh[(size_t)i * 4],             reinterpret_cast<const float4*>(qa)[i]);
        h4store(&g_Xh[(size_t)(i + PACK_N4) * 4], reinterpret_cast<const float4*>(qb)[i]);
        return;
    }
    int k = i - PACK_N4;
    if (k < 196608) {
        int which = k >> 16, off = k & 65535;
        const float4* src = reinterpret_cast<const float4*>(which == 0 ? Wq : (which == 1 ? Wk : Wv));
        h4store(&g_Wqkvh[(size_t)k * 4], src[off]);
    } else if (k < 262144) {
        int j = k - 196608;
        h4store(&g_Woh[(size_t)j * 4], reinterpret_cast<const float4*>(Wo)[j]);
    } else if (k < 524288) {
        int j = k - 262144;
        h4store(&g_W1h[(size_t)j * 4], reinterpret_cast<const float4*>(W1)[j]);
    } else if (k < 786432) {
        int j = k - 524288;
        h4store(&g_W2h[(size_t)j * 4], reinterpret_cast<const float4*>(W2)[j]);
    } else if (k < 786816) {
        int j = k - 786432;
        const float4* src = reinterpret_cast<const float4*>(j < 128 ? bq : (j < 256 ? bk : bv));
        reinterpret_cast<float4*>(g_bqkv)[j] = src[j & 127];
    }
}

// ============ fp16 mma.sync GEMM (cp.async 3-stage, BK=64, padded rows) =======
// C[M,N] = A[M,K] @ W[N,K]^T + bias (fp32 accum). 128x128 CTA tile, BK=64,
// 128 threads (4 warps, 2x2), warp tile 64x64. Row = 64 halves (128B) + 16B pad
// = 144B: ldmatrix row-addresses hit 8 distinct 16B bank-groups.
#define ROWB 144
#define OPER_BYTES (128 * ROWB)      // 18432
#define STAGE_BYTES (2 * OPER_BYTES) // 36864
#define NSTAGE 3

__global__ void __launch_bounds__(128, 2)
hgemm_kernel(const __half* __restrict__ A, const __half* __restrict__ W,
             const float* __restrict__ bias, void* __restrict__ Cv,
             int K, int N, int relu, int outHalf)
{
    extern __shared__ char smem[];

    const int tid  = threadIdx.x;
    const int wid  = tid >> 5;
    const int lane = tid & 31;
    const int g    = lane >> 2;
    const int tg   = lane & 3;
    const int wm   = wid >> 1;
    const int wn   = wid & 1;
    const int bm = blockIdx.y, bn = blockIdx.x;

    const __half* Ag = A + (size_t)bm * 128 * K;
    const __half* Wg = W + (size_t)bn * 128 * K;

    const uint32_t sb = smem_u32(smem);

    // cp.async mapping: 128 rows x 8 segs (16B) per operand; 8 iters/operand
    uint32_t stOff[8];
    size_t   gOff[8];
#pragma unroll
    for (int i = 0; i < 8; i++) {
        int idx = i * 128 + tid;
        int row = idx >> 3, seg = idx & 7;
        stOff[i] = (uint32_t)(row * ROWB + seg * 16);
        gOff[i]  = (size_t)row * K + seg * 8;
    }

    const int rowA = ((lane >> 3) & 1) * 8 + (lane & 7);
    const int cA   = (lane >> 4);
    const int rowB = ((lane >> 4) & 1) * 8 + (lane & 7);
    const int cB   = ((lane >> 3) & 1);

    uint32_t aRowOff[4], bRowOff[4];
#pragma unroll
    for (int mi = 0; mi < 4; mi++)
        aRowOff[mi] = (uint32_t)((wm * 64 + mi * 16 + rowA) * ROWB);
#pragma unroll
    for (int n2 = 0; n2 < 4; n2++)
        bRowOff[n2] = (uint32_t)(OPER_BYTES + (wn * 64 + n2 * 16 + rowB) * ROWB);

    float acc[4][8][4];
#pragma unroll
    for (int mi = 0; mi < 4; mi++)
#pragma unroll
        for (int ni = 0; ni < 8; ni++)
#pragma unroll
            for (int r = 0; r < 4; r++) acc[mi][ni][r] = 0.f;

    const int NC = K >> 6;   // chunks of 64

#pragma unroll
    for (int p = 0; p < 2; p++) {
        uint32_t st = sb + p * STAGE_BYTES;
        size_t go = (size_t)p * 64;
#pragma unroll
        for (int i = 0; i < 8; i++) {
            cp16(st + stOff[i],              Ag + gOff[i] + go);
            cp16(st + OPER_BYTES + stOff[i], Wg + gOff[i] + go);
        }
        asm volatile("cp.async.commit_group;" ::: "memory");
    }

    for (int c = 0; c < NC; ++c) {
        asm volatile("cp.async.wait_group 1;" ::: "memory");
        __syncthreads();

        if (c + 2 < NC) {
            int s2 = (c + 2) % NSTAGE;
            uint32_t st = sb + s2 * STAGE_BYTES;
            size_t go = (size_t)(c + 2) * 64;
#pragma unroll
            for (int i = 0; i < 8; i++) {
                cp16(st + stOff[i],              Ag + gOff[i] + go);
                cp16(st + OPER_BYTES + stOff[i], Wg + gOff[i] + go);
            }
        }
        asm volatile("cp.async.commit_group;" ::: "memory");

        const uint32_t base = sb + (c % NSTAGE) * STAGE_BYTES;
#pragma unroll
        for (int ks = 0; ks < 4; ks++) {
            uint32_t a[4][4];
#pragma unroll
            for (int mi = 0; mi < 4; mi++)
                ldsm4(a[mi][0], a[mi][1], a[mi][2], a[mi][3],
                      base + aRowOff[mi] + (uint32_t)((ks * 2 + cA) * 16));
            uint32_t b[4][4];
#pragma unroll
            for (int n2 = 0; n2 < 4; n2++)
                ldsm4(b[n2][0], b[n2][1], b[n2][2], b[n2][3],
                      base + bRowOff[n2] + (uint32_t)((ks * 2 + cB) * 16));
#pragma unroll
            for (int mi = 0; mi < 4; mi++)
#pragma unroll
                for (int ni = 0; ni < 8; ni++) {
                    const uint32_t b0 = (ni & 1) ? b[ni >> 1][2] : b[ni >> 1][0];
                    const uint32_t b1 = (ni & 1) ? b[ni >> 1][3] : b[ni >> 1][1];
                    mma_f16(acc[mi][ni][0], acc[mi][ni][1], acc[mi][ni][2], acc[mi][ni][3],
                            a[mi][0], a[mi][1], a[mi][2], a[mi][3], b0, b1);
                }
        }
    }

    const float2* bias2 = reinterpret_cast<const float2*>(bias);
#pragma unroll
    for (int mi = 0; mi < 4; mi++) {
        int r0 = bm * 128 + wm * 64 + mi * 16 + g;
#pragma unroll
        for (int ni = 0; ni < 8; ni++) {
            int col = bn * 128 + wn * 64 + ni * 8 + 2 * tg;
            float2 bv = __ldg(&bias2[col >> 1]);
            float2 o0, o1;
            o0.x = acc[mi][ni][0] + bv.x;
            o0.y = acc[mi][ni][1] + bv.y;
            o1.x = acc[mi][ni][2] + bv.x;
            o1.y = acc[mi][ni][3] + bv.y;
            if (relu) {
                o0.x = fmaxf(o0.x, 0.f); o0.y = fmaxf(o0.y, 0.f);
                o1.x = fmaxf(o1.x, 0.f); o1.y = fmaxf(o1.y, 0.f);
            }
            if (outHalf) {
                __half* C = (__half*)Cv;
                *reinterpret_cast<__half2*>(C + (size_t)r0 * N + col) =
                    __floats2half2_rn(o0.x, o0.y);
                *reinterpret_cast<__half2*>(C + (size_t)(r0 + 8) * N + col) =
                    __floats2half2_rn(o1.x, o1.y);
            } else {
                float* C = (float*)Cv;
                *reinterpret_cast<float2*>(C + (size_t)r0 * N + col) = o0;
                *reinterpret_cast<float2*>(C + (size_t)(r0 + 8) * N + col) = o1;
            }
        }
    }
}

// ---------------- S partial (tensor core, cp.async double-buffered) -----------
// Each CTA: 256 rows (8 tiles of 32). 4 warps, warp w: e in [w*16, w*16+16).
#define SROW 72   // halves per smem row (144B = 9*16B, conflict-free trans ldsm)
#define STILES 8  // 256 rows / 32
__global__ void __launch_bounds__(128)
s_partial_kernel()
{
    const int bh = blockIdx.x;
    const int j  = blockIdx.y;
    const int b = bh >> 3;
    const int h = bh & 7;

    __shared__ __half Kt[2][32][SROW];
    __shared__ __half Vt[2][32][SROW];

    const int tid = threadIdx.x;
    const int wid = tid >> 5;
    const int lane = tid & 31;
    const int g = lane >> 2;
    const int tg = lane & 3;
    const int e0 = wid * 16;

    const int aRow = ((lane >> 4) & 1) * 8 + (lane & 7);
    const int aCol = e0 + ((lane >> 3) & 1) * 8;
    const int bRow = ((lane >> 3) & 1) * 8 + (lane & 7);
    const int bColOff = ((lane >> 4) & 1) * 8;

    uint32_t kb[2] = { smem_u32(Kt[0]), smem_u32(Kt[1]) };
    uint32_t vb[2] = { smem_u32(Vt[0]), smem_u32(Vt[1]) };

    const size_t koff = 512 + (size_t)h * DH;
    const size_t voff = 1024 + (size_t)h * DH;

    const int cRow0 = tid >> 3;
    const int cSeg  = tid & 7;
    const uint32_t cOff0 = (uint32_t)(cRow0 * SROW + cSeg * 8) * 2;
    const uint32_t cOff1 = (uint32_t)((cRow0 + 16) * SROW + cSeg * 8) * 2;

    float acc[8][4];
#pragma unroll
    for (int ni = 0; ni < 8; ni++)
#pragma unroll
        for (int r = 0; r < 4; r++) acc[ni][r] = 0.f;

    {
        const int g0 = j * (STILES * 32);
        const int s = g0 >> 11;
        const int br = (s * 4 + b) * 2048 + (g0 & 2047);
        size_t r0off = (size_t)(br + cRow0) * QKVN;
        size_t r1off = (size_t)(br + cRow0 + 16) * QKVN;
        cp16(kb[0] + cOff0, &g_QKVh[r0off + koff + cSeg * 8]);
        cp16(kb[0] + cOff1, &g_QKVh[r1off + koff + cSeg * 8]);
        cp16(vb[0] + cOff0, &g_QKVh[r0off + voff + cSeg * 8]);
        cp16(vb[0] + cOff1, &g_QKVh[r1off + voff + cSeg * 8]);
        asm volatile("cp.async.commit_group;" ::: "memory");
    }

    for (int t = 0; t < STILES; ++t) {
        if (t + 1 < STILES) {
            int buf = (t + 1) & 1;
            const int g0 = j * (STILES * 32) + (t + 1) * 32;
            const int s = g0 >> 11;
            const int br = (s * 4 + b) * 2048 + (g0 & 2047);
            size_t r0off = (size_t)(br + cRow0) * QKVN;
            size_t r1off = (size_t)(br + cRow0 + 16) * QKVN;
            cp16(kb[buf] + cOff0, &g_QKVh[r0off + koff + cSeg * 8]);
            cp16(kb[buf] + cOff1, &g_QKVh[r1off + koff + cSeg * 8]);
            cp16(vb[buf] + cOff0, &g_QKVh[r0off + voff + cSeg * 8]);
            cp16(vb[buf] + cOff1, &g_QKVh[r1off + voff + cSeg * 8]);
            asm volatile("cp.async.commit_group;" ::: "memory");
            asm volatile("cp.async.wait_group 1;" ::: "memory");
        } else {
            asm volatile("cp.async.commit_group;" ::: "memory");
            asm volatile("cp.async.wait_group 0;" ::: "memory");
        }
        __syncthreads();

        const int cur = t & 1;
        const uint32_t aAddr0 = kb[cur] + (uint32_t)(aRow * SROW + aCol) * 2;
        const uint32_t bAddr0 = vb[cur] + (uint32_t)(bRow * SROW + bColOff) * 2;
#pragma unroll
        for (int ks = 0; ks < 2; ks++) {
            const uint32_t lOff = (uint32_t)(ks * 16 * SROW) * 2;
            uint32_t a[4];
            ldsm4t(a[0], a[1], a[2], a[3], aAddr0 + lOff);
            uint32_t vB[4][4];
#pragma unroll
            for (int n2 = 0; n2 < 4; n2++)
                ldsm4t(vB[n2][0], vB[n2][1], vB[n2][2], vB[n2][3],
                       bAddr0 + lOff + (uint32_t)(n2 * 16) * 2);
#pragma unroll
            for (int ni = 0; ni < 8; ni++) {
                const uint32_t b0 = (ni & 1) ? vB[ni >> 1][2] : vB[ni >> 1][0];
                const uint32_t b1 = (ni & 1) ? vB[ni >> 1][3] : vB[ni >> 1][1];
                mma_f16(acc[ni][0], acc[ni][1], acc[ni][2], acc[ni][3],
                        a[0], a[1], a[2], a[3], b0, b1);
            }
        }
        __syncthreads();
    }

    float* Sp = &g_Spart[((size_t)j * 32 + bh) * (DH * DH)];
#pragma unroll
    for (int ni = 0; ni < 8; ni++) {
        int col = (ni >> 1) * 16 + (ni & 1) * 8 + 2 * tg;
        int e = e0 + g;
        *reinterpret_cast<float2*>(&Sp[e * DH + col]) = make_float2(acc[ni][0], acc[ni][1]);
        *reinterpret_cast<float2*>(&Sp[(e + 8) * DH + col]) = make_float2(acc[ni][2], acc[ni][3]);
    }
}

// ---------------- S reduce -> transposed fp16 hi/lo (parallelized) -------------
__global__ void __launch_bounds__(128)
s_reduce_kernel()
{
    const int bh = blockIdx.x;
    const int idx4 = blockIdx.y * 128 + threadIdx.x;   // 0..1023
    const size_t base = (size_t)bh * (DH * DH);
    const int e = idx4 >> 4;
    const int d0 = (idx4 & 15) * 4;

    float4 acc = make_float4(0.f, 0.f, 0.f, 0.f);
#pragma unroll
    for (int j = 0; j < NSLICE; j++) {
        float4 v = reinterpret_cast<const float4*>(
            &g_Spart[((size_t)j * 32 + bh) * (DH * DH)])[idx4];
        acc.x += v.x; acc.y += v.y; acc.z += v.z; acc.w += v.w;
    }
    float vals[4] = {acc.x, acc.y, acc.z, acc.w};
#pragma unroll
    for (int k = 0; k < 4; k++) {
        __half hi = __float2half_rn(vals[k]);
        float lo = vals[k] - __half2float(hi);
        g_Shi[base + (size_t)(d0 + k) * DH + e] = hi;
        g_Slo[base + (size_t)(d0 + k) * DH + e] = __float2half_rn(lo);
    }
}

// ---------------- Q @ S (tensor core, split-precision S) ----------------------
__global__ void __launch_bounds__(128)
qs_kernel()
{
    const int h = blockIdx.y;
    const int r0 = blockIdx.x * 128;
    const int b = (r0 >> 11) & 3;

    __shared__ __half Qs[128][SROW];
    __shared__ __half Sh[64][SROW];
    __shared__ __half Sl[64][SROW];

    const int tid = threadIdx.x;
    const int wid = tid >> 5;
    const int lane = tid & 31;
    const int g = lane >> 2;
    const int tg = lane & 3;
    const int m0 = wid * 32;

#pragma unroll
    for (int i = 0; i < 8; i++) {
        int idx = i * 128 + tid;
        int row = idx >> 3, seg = idx & 7;
        *reinterpret_cast<uint4*>(&Qs[row][seg * 8]) =
            *reinterpret_cast<const uint4*>(
                &g_QKVh[(size_t)(r0 + row) * QKVN + (size_t)h * DH + seg * 8]);
    }
    const size_t sbase = (size_t)(b * 8 + h) * (DH * DH);
#pragma unroll
    for (int i = 0; i < 4; i++) {
        int idx = i * 128 + tid;
        int row = idx >> 3, seg = idx & 7;
        *reinterpret_cast<uint4*>(&Sh[row][seg * 8]) =
            *reinterpret_cast<const uint4*>(&g_Shi[sbase + (size_t)row * DH + seg * 8]);
        *reinterpret_cast<uint4*>(&Sl[row][seg * 8]) =
            *reinterpret_cast<const uint4*>(&g_Slo[sbase + (size_t)row * DH + seg * 8]);
    }
    __syncthreads();

    const int rowA = ((lane >> 3) & 1) * 8 + (lane & 7);
    const int cA   = (lane >> 4);
    const int rowB = ((lane >> 4) & 1) * 8 + (lane & 7);
    const int cB   = ((lane >> 3) & 1);

    const uint32_t qb  = smem_u32(Qs);
    const uint32_t shb = smem_u32(Sh);
    const uint32_t slb = smem_u32(Sl);

    float acc[2][8][4];
#pragma unroll
    for (int mi = 0; mi < 2; mi++)
#pragma unroll
        for (int ni = 0; ni < 8; ni++)
#pragma unroll
            for (int r = 0; r < 4; r++) acc[mi][ni][r] = 0.f;

#pragma unroll
    for (int ks = 0; ks < 4; ks++) {
        const uint32_t kByte = (uint32_t)(ks * 32);
        uint32_t a[2][4];
#pragma unroll
        for (int mi = 0; mi < 2; mi++)
            ldsm4(a[mi][0], a[mi][1], a[mi][2], a[mi][3],
                  qb + (uint32_t)((m0 + mi * 16 + rowA) * SROW) * 2 + kByte + cA * 16);
        uint32_t bh_[4][4], bl_[4][4];
#pragma unroll
        for (int n2 = 0; n2 < 4; n2++) {
            uint32_t ro = (uint32_t)((n2 * 16 + rowB) * SROW) * 2 + kByte + cB * 16;
            ldsm4(bh_[n2][0], bh_[n2][1], bh_[n2][2], bh_[n2][3], shb + ro);
            ldsm4(bl_[n2][0], bl_[n2][1], bl_[n2][2], bl_[n2][3], slb + ro);
        }
#pragma unroll
        for (int mi = 0; mi < 2; mi++)
#pragma unroll
            for (int ni = 0; ni < 8; ni++) {
                const uint32_t h0 = (ni & 1) ? bh_[ni >> 1][2] : bh_[ni >> 1][0];
                const uint32_t h1 = (ni & 1) ? bh_[ni >> 1][3] : bh_[ni >> 1][1];
                const uint32_t l0 = (ni & 1) ? bl_[ni >> 1][2] : bl_[ni >> 1][0];
                const uint32_t l1 = (ni & 1) ? bl_[ni >> 1][3] : bl_[ni >> 1][1];
                mma_f16(acc[mi][ni][0], acc[mi][ni][1], acc[mi][ni][2], acc[mi][ni][3],
                        a[mi][0], a[mi][1], a[mi][2], a[mi][3], h0, h1);
                mma_f16(acc[mi][ni][0], acc[mi][ni][1], acc[mi][ni][2], acc[mi][ni][3],
                        a[mi][0], a[mi][1], a[mi][2], a[mi][3], l0, l1);
            }
    }

#pragma unroll
    for (int mi = 0; mi < 2; mi++) {
        int row = r0 + m0 + mi * 16 + g;
#pragma unroll
        for (int ni = 0; ni < 8; ni++) {
            int col = h * DH + (ni >> 1) * 16 + (ni & 1) * 8 + 2 * tg;
            *reinterpret_cast<__half2*>(&g_attnh[(size_t)row * DIM + col]) =
                __floats2half2_rn(acc[mi][ni][0], acc[mi][ni][1]);
            *reinterpret_cast<__half2*>(&g_attnh[(size_t)(row + 8) * DIM + col]) =
                __floats2half2_rn(acc[mi][ni][2], acc[mi][ni][3]);
        }
    }
}

// ---------------- fused residual + LayerNorm ----------------------------------
__global__ void __launch_bounds__(128)
ln_kernel(const float* __restrict__ inA, const float* __restrict__ inB,
          const float* __restrict__ R,
          const float* __restrict__ gamma, const float* __restrict__ beta,
          float* __restrict__ out, __half* __restrict__ outh, int concat)
{
    const int row = blockIdx.x;
    const int tid = threadIdx.x;
    const int c = tid * 4;
    const size_t off = (size_t)row * DIM + c;

    float4 a;
    if (concat) {
        a = *reinterpret_cast<const float4*>(inA + off);
    } else {
        const float* src = (row < HALF_M) ? inA : inB;
        int rl = row & (HALF_M - 1);
        a = *reinterpret_cast<const float4*>(src + (size_t)rl * DIM + c);
    }
    float4 r = *reinterpret_cast<const float4*>(R + off);
    float v0 = a.x + r.x, v1 = a.y + r.y, v2 = a.z + r.z, v3 = a.w + r.w;

    float s = v0 + v1 + v2 + v3;
    float q = v0 * v0 + v1 * v1 + v2 * v2 + v3 * v3;
#pragma unroll
    for (int o = 16; o > 0; o >>= 1) {
        s += __shfl_xor_sync(0xffffffffu, s, o);
        q += __shfl_xor_sync(0xffffffffu, q, o);
    }
    __shared__ float ss[4], sq[4];
    if ((tid & 31) == 0) { ss[tid >> 5] = s; sq[tid >> 5] = q; }
    __syncthreads();
    s = ss[0] + ss[1] + ss[2] + ss[3];
    q = sq[0] + sq[1] + sq[2] + sq[3];

    const float mean = s * (1.f / DIM);
    const float var = q * (1.f / DIM) - mean * mean;
    const float rstd = rsqrtf(var + LN_EPS);

    float4 gv = *reinterpret_cast<const float4*>(gamma + c);
    float4 bv = *reinterpret_cast<const float4*>(beta + c);
    float4 o;
    o.x = (v0 - mean) * rstd * gv.x + bv.x;
    o.y = (v1 - mean) * rstd * gv.y + bv.y;
    o.z = (v2 - mean) * rstd * gv.z + bv.z;
    o.w = (v3 - mean) * rstd * gv.w + bv.w;

    if (!concat) {
        *reinterpret_cast<float4*>(out + off) = o;
        if (outh) h4store(outh + off, o);
    } else {
        int sdx = row >> 13;
        int rem = row & 8191;
        *reinterpret_cast<float4*>(out + (size_t)rem * 1024 + sdx * 512 + c) = o;
    }
}

// ---------------- launch ------------------------------------------------------
extern "C" void kernel_launch(void* const* d_in, const int* in_sizes, int n_in,
                              void* d_out, int out_size)
{
    (void)in_sizes; (void)n_in; (void)out_size;
    const float* question = (const float*)d_in[0];
    const float* query    = (const float*)d_in[1];
    const float* Wq = (const float*)d_in[2];
    const float* bq = (const float*)d_in[3];
    const float* Wk = (const float*)d_in[4];
    const float* bk = (const float*)d_in[5];
    const float* Wv = (const float*)d_in[6];
    const float* bv = (const float*)d_in[7];
    const float* Wo = (const float*)d_in[8];
    const float* bo = (const float*)d_in[9];
    const float* ln_g = (const float*)d_in[10];
    const float* ln_b = (const float*)d_in[11];
    const float* W1 = (const float*)d_in[12];
    const float* b1 = (const float*)d_in[13];
    const float* W2 = (const float*)d_in[14];
    const float* b2 = (const float*)d_in[15];
    float* out = (float*)d_out;

    float *proj, *x1, *ff, *bqkv;
    __half *Xh, *QKVh, *attnh, *x1h, *h1h, *Wqkvh, *Woh, *W1h, *W2h;
    cudaGetSymbolAddress((void**)&Xh,    g_Xh);
    cudaGetSymbolAddress((void**)&QKVh,  g_QKVh);
    cudaGetSymbolAddress((void**)&attnh, g_attnh);
    cudaGetSymbolAddress((void**)&proj,  g_proj);
    cudaGetSymbolAddress((void**)&x1,    g_x1);
    cudaGetSymbolAddress((void**)&x1h,   g_x1h);
    cudaGetSymbolAddress((void**)&h1h,   g_h1h);
    cudaGetSymbolAddress((void**)&ff,    g_ff);
    cudaGetSymbolAddress((void**)&Wqkvh, g_Wqkvh);
    cudaGetSymbolAddress((void**)&bqkv,  g_bqkv);
    cudaGetSymbolAddress((void**)&Woh,   g_Woh);
    cudaGetSymbolAddress((void**)&W1h,   g_W1h);
    cudaGetSymbolAddress((void**)&W2h,   g_W2h);

    const int SMEM_GEMM = NSTAGE * STAGE_BYTES;   // 110592 bytes
    cudaFuncSetAttribute(hgemm_kernel, cudaFuncAttributeMaxDynamicSharedMemorySize, SMEM_GEMM);

    // 0. fused prep + pack (one launch)
    const int PREP_TOTAL = PACK_N4 + 786816;
    prep_pack_kernel<<<(PREP_TOTAL + 255) / 256, 256>>>(
        question, query, Wq, Wk, Wv, Wo, W1, W2, bq, bk, bv);

    // 1. fused QKV projection: [16384 x 1536], fp16 out
    hgemm_kernel<<<dim3(QKVN / 128, MTOT / 128), 128, SMEM_GEMM>>>(
        Xh, Wqkvh, bqkv, QKVh, DIM, QKVN, 0, 1);

    // 2. shared linear-attention state (tensor core + parallel reduce)
    s_partial_kernel<<<dim3(NB * NH, NSLICE), 128>>>();
    s_reduce_kernel<<<dim3(NB * NH, 8), 128>>>();

    // 3. attn = Q @ S (tensor core, split S)
    qs_kernel<<<dim3(MTOT / 128, NH), 128>>>();

    // 4. output projection (fp32 out)
    hgemm_kernel<<<dim3(DIM / 128, MTOT / 128), 128, SMEM_GEMM>>>(
        attnh, Woh, bo, proj, DIM, DIM, 0, 0);

    // 5. LN1: residual read directly from question/query; x1 fp32 + x1h fp16
    ln_kernel<<<MTOT, 128>>>(question, query, proj, ln_g, ln_b, x1, x1h, 0);

    // 6. FF1 (ReLU fused, fp16 out)
    hgemm_kernel<<<dim3(PF / 128, MTOT / 128), 128, SMEM_GEMM>>>(
        x1h, W1h, b1, h1h, DIM, PF, 1, 1);

    // 7. FF2 (fp32 out)
    hgemm_kernel<<<dim3(DIM / 128, MTOT / 128), 128, SMEM_GEMM>>>(
        h1h, W2h, b2, ff, PF, DIM, 0, 0);

    // 8. LN2 + residual + concat
    ln_kernel<<<MTOT, 128>>>(x1, nullptr, ff, ln_g, ln_b, out, nullptr, 1);
}

// round 16
// speedup vs baseline: 1.0561x; 1.0561x over previous
#include <cuda_runtime.h>
#include <cuda_fp16.h>
#include <cstdint>

// Problem constants
#define MTOT 16384      // 2 streams * B(4) * L(2048)
#define HALF_M 8192
#define DIM 512
#define PF 2048
#define QKVN 1536
#define NB 4
#define NH 8
#define DH 64
#define LN_EPS 1e-5f
#define NSLICE 16

// ---------------- scratch (static device globals; no allocation) -------------
__device__ __half g_Xh   [MTOT * DIM];    // fp16 stacked input (GEMM operand)
__device__ __half g_QKVh [MTOT * QKVN];   // fused QKV output (fp16) [Q|K|V]
__device__ __half g_attnh[MTOT * DIM];    // fp16 attn (Wo operand)
__device__ float  g_proj [MTOT * DIM];
__device__ float  g_x1   [MTOT * DIM];    // exact (LN2 residual)
__device__ __half g_x1h  [MTOT * DIM];    // fp16 (FF1 operand)
__device__ __half g_h1h  [MTOT * PF];     // fp16 FF intermediate
__device__ float  g_ff   [MTOT * DIM];
__device__ float  g_Spart[NSLICE * NB * NH * DH * DH];
__device__ __half g_Shi  [NB * NH * DH * DH];   // S^T hi (fp16), layout [bh][d][e]
__device__ __half g_Slo  [NB * NH * DH * DH];   // S^T lo residual (fp16)
// packed fp16 weights + fp32 bias
__device__ __half g_Wqkvh[QKVN * DIM];
__device__ float  g_bqkv [QKVN];
__device__ __half g_Woh  [DIM * DIM];
__device__ __half g_W1h  [PF * DIM];
__device__ __half g_W2h  [DIM * PF];

// ---------------- helpers ----------------------------------------------------
__device__ __forceinline__ uint32_t smem_u32(const void* p) {
    uint32_t a;
    asm("{ .reg .u64 t; cvta.to.shared.u64 t, %1; cvt.u32.u64 %0, t; }" : "=r"(a) : "l"(p));
    return a;
}
__device__ __forceinline__ void mma_f16(float& c0, float& c1, float& c2, float& c3,
                                        uint32_t a0, uint32_t a1, uint32_t a2, uint32_t a3,
                                        uint32_t b0, uint32_t b1)
{
    asm volatile(
        "mma.sync.aligned.m16n8k16.row.col.f32.f16.f16.f32 "
        "{%0,%1,%2,%3}, {%4,%5,%6,%7}, {%8,%9}, {%0,%1,%2,%3};"
        : "+f"(c0), "+f"(c1), "+f"(c2), "+f"(c3)
        : "r"(a0), "r"(a1), "r"(a2), "r"(a3), "r"(b0), "r"(b1));
}
__device__ __forceinline__ void ldsm4(uint32_t& r0, uint32_t& r1, uint32_t& r2, uint32_t& r3,
                                      uint32_t addr)
{
    asm volatile("ldmatrix.sync.aligned.m8n8.x4.shared.b16 {%0,%1,%2,%3}, [%4];"
                 : "=r"(r0), "=r"(r1), "=r"(r2), "=r"(r3) : "r"(addr));
}
__device__ __forceinline__ void ldsm4t(uint32_t& r0, uint32_t& r1, uint32_t& r2, uint32_t& r3,
                                       uint32_t addr)
{
    asm volatile("ldmatrix.sync.aligned.m8n8.x4.trans.shared.b16 {%0,%1,%2,%3}, [%4];"
                 : "=r"(r0), "=r"(r1), "=r"(r2), "=r"(r3) : "r"(addr));
}
__device__ __forceinline__ void cp16(uint32_t saddr, const void* g) {
    asm volatile("cp.async.cg.shared.global [%0], [%1], 16;" :: "r"(saddr), "l"(g) : "memory");
}
__device__ __forceinline__ void h4store(__half* dst, float4 v) {
    __half2* d = reinterpret_cast<__half2*>(dst);
    d[0] = __floats2half2_rn(v.x, v.y);
    d[1] = __floats2half2_rn(v.z, v.w);
}

// ---------------- fused prep + pack (one launch) -------------------------------
#define PACK_N4 (HALF_M * DIM / 4)   // 1048576
__global__ void prep_pack_kernel(const float* __restrict__ qa, const float* __restrict__ qb,
                                 const float* __restrict__ Wq, const float* __restrict__ Wk,
                                 const float* __restrict__ Wv, const float* __restrict__ Wo,
                                 const float* __restrict__ W1, const float* __restrict__ W2,
                                 const float* __restrict__ bq, const float* __restrict__ bk,
                                 const float* __restrict__ bv)
{
    int i = blockIdx.x * blockDim.x + threadIdx.x;
    if (i < PACK_N4) {
        h4store(&g_Xh[(size_t)i * 4],             reinterpret_cast<const float4*>(qa)[i]);
        h4store(&g_Xh[(size_t)(i + PACK_N4) * 4], reinterpret_cast<const float4*>(qb)[i]);
        return;
    }
    int k = i - PACK_N4;
    if (k < 196608) {
        int which = k >> 16, off = k & 65535;
        const float4* src = reinterpret_cast<const float4*>(which == 0 ? Wq : (which == 1 ? Wk : Wv));
        h4store(&g_Wqkvh[(size_t)k * 4], src[off]);
    } else if (k < 262144) {
        int j = k - 196608;
        h4store(&g_Woh[(size_t)j * 4], reinterpret_cast<const float4*>(Wo)[j]);
    } else if (k < 524288) {
        int j = k - 262144;
        h4store(&g_W1h[(size_t)j * 4], reinterpret_cast<const float4*>(W1)[j]);
    } else if (k < 786432) {
        int j = k - 524288;
        h4store(&g_W2h[(size_t)j * 4], reinterpret_cast<const float4*>(W2)[j]);
    } else if (k < 786816) {
        int j = k - 786432;
        const float4* src = reinterpret_cast<const float4*>(j < 128 ? bq : (j < 256 ? bk : bv));
        reinterpret_cast<float4*>(g_bqkv)[j] = src[j & 127];
    }
}

// ============ fp16 mma.sync GEMM (cp.async 3-stage, padded-row smem) ==========
// C[M,N] = A[M,K] @ W[N,K]^T + bias (fp32 accum). 128x128 CTA tile, BK=32,
// 128 threads (4 warps, 2x2), warp tile 64x64.
#define ROWB 80
#define OPER_BYTES (128 * ROWB)      // 10240
#define STAGE_BYTES (2 * OPER_BYTES) // 20480
#define NSTAGE 3

__global__ void __launch_bounds__(128, 2)
hgemm_kernel(const __half* __restrict__ A, const __half* __restrict__ W,
             const float* __restrict__ bias, void* __restrict__ Cv,
             int K, int N, int relu, int outHalf)
{
    extern __shared__ char smem[];

    const int tid  = threadIdx.x;
    const int wid  = tid >> 5;
    const int lane = tid & 31;
    const int g    = lane >> 2;
    const int tg   = lane & 3;
    const int wm   = wid >> 1;
    const int wn   = wid & 1;
    const int bm = blockIdx.y, bn = blockIdx.x;

    const __half* Ag = A + (size_t)bm * 128 * K;
    const __half* Wg = W + (size_t)bn * 128 * K;

    const uint32_t sb = smem_u32(smem);

    uint32_t stOff[4];
    size_t   gOff[4];
#pragma unroll
    for (int i = 0; i < 4; i++) {
        int idx = i * 128 + tid;
        int row = idx >> 2, seg = idx & 3;
        stOff[i] = (uint32_t)(row * ROWB + seg * 16);
        gOff[i]  = (size_t)row * K + seg * 8;
    }

    const int rowA = ((lane >> 3) & 1) * 8 + (lane & 7);
    const int cA   = (lane >> 4);
    const int rowB = ((lane >> 4) & 1) * 8 + (lane & 7);
    const int cB   = ((lane >> 3) & 1);

    uint32_t aRowOff[4], bRowOff[4];
#pragma unroll
    for (int mi = 0; mi < 4; mi++)
        aRowOff[mi] = (uint32_t)((wm * 64 + mi * 16 + rowA) * ROWB);
#pragma unroll
    for (int n2 = 0; n2 < 4; n2++)
        bRowOff[n2] = (uint32_t)(OPER_BYTES + (wn * 64 + n2 * 16 + rowB) * ROWB);

    float acc[4][8][4];
#pragma unroll
    for (int mi = 0; mi < 4; mi++)
#pragma unroll
        for (int ni = 0; ni < 8; ni++)
#pragma unroll
            for (int r = 0; r < 4; r++) acc[mi][ni][r] = 0.f;

    const int NC = K >> 5;

#pragma unroll
    for (int p = 0; p < 2; p++) {
        uint32_t st = sb + p * STAGE_BYTES;
        size_t go = (size_t)p * 32;
#pragma unroll
        for (int i = 0; i < 4; i++) {
            cp16(st + stOff[i],              Ag + gOff[i] + go);
            cp16(st + OPER_BYTES + stOff[i], Wg + gOff[i] + go);
        }
        asm volatile("cp.async.commit_group;" ::: "memory");
    }

    for (int c = 0; c < NC; ++c) {
        asm volatile("cp.async.wait_group 1;" ::: "memory");
        __syncthreads();

        if (c + 2 < NC) {
            int s2 = (c + 2) % NSTAGE;
            uint32_t st = sb + s2 * STAGE_BYTES;
            size_t go = (size_t)(c + 2) * 32;
#pragma unroll
            for (int i = 0; i < 4; i++) {
                cp16(st + stOff[i],              Ag + gOff[i] + go);
                cp16(st + OPER_BYTES + stOff[i], Wg + gOff[i] + go);
            }
        }
        asm volatile("cp.async.commit_group;" ::: "memory");

        const uint32_t base = sb + (c % NSTAGE) * STAGE_BYTES;
#pragma unroll
        for (int ks = 0; ks < 2; ks++) {
            uint32_t a[4][4];
#pragma unroll
            for (int mi = 0; mi < 4; mi++)
                ldsm4(a[mi][0], a[mi][1], a[mi][2], a[mi][3],
                      base + aRowOff[mi] + (uint32_t)((ks * 2 + cA) * 16));
            uint32_t b[4][4];
#pragma unroll
            for (int n2 = 0; n2 < 4; n2++)
                ldsm4(b[n2][0], b[n2][1], b[n2][2], b[n2][3],
                      base + bRowOff[n2] + (uint32_t)((ks * 2 + cB) * 16));
#pragma unroll
            for (int mi = 0; mi < 4; mi++)
#pragma unroll
                for (int ni = 0; ni < 8; ni++) {
                    const uint32_t b0 = (ni & 1) ? b[ni >> 1][2] : b[ni >> 1][0];
                    const uint32_t b1 = (ni & 1) ? b[ni >> 1][3] : b[ni >> 1][1];
                    mma_f16(acc[mi][ni][0], acc[mi][ni][1], acc[mi][ni][2], acc[mi][ni][3],
                            a[mi][0], a[mi][1], a[mi][2], a[mi][3], b0, b1);
                }
        }
    }

    const float2* bias2 = reinterpret_cast<const float2*>(bias);
#pragma unroll
    for (int mi = 0; mi < 4; mi++) {
        int r0 = bm * 128 + wm * 64 + mi * 16 + g;
#pragma unroll
        for (int ni = 0; ni < 8; ni++) {
            int col = bn * 128 + wn * 64 + ni * 8 + 2 * tg;
            float2 bv = __ldg(&bias2[col >> 1]);
            float2 o0, o1;
            o0.x = acc[mi][ni][0] + bv.x;
            o0.y = acc[mi][ni][1] + bv.y;
            o1.x = acc[mi][ni][2] + bv.x;
            o1.y = acc[mi][ni][3] + bv.y;
            if (relu) {
                o0.x = fmaxf(o0.x, 0.f); o0.y = fmaxf(o0.y, 0.f);
                o1.x = fmaxf(o1.x, 0.f); o1.y = fmaxf(o1.y, 0.f);
            }
            if (outHalf) {
                __half* C = (__half*)Cv;
                *reinterpret_cast<__half2*>(C + (size_t)r0 * N + col) =
                    __floats2half2_rn(o0.x, o0.y);
                *reinterpret_cast<__half2*>(C + (size_t)(r0 + 8) * N + col) =
                    __floats2half2_rn(o1.x, o1.y);
            } else {
                float* C = (float*)Cv;
                *reinterpret_cast<float2*>(C + (size_t)r0 * N + col) = o0;
                *reinterpret_cast<float2*>(C + (size_t)(r0 + 8) * N + col) = o1;
            }
        }
    }
}

// ---------------- S partial (tensor core, cp.async double-buffered) -----------
// Each CTA: 256 rows (8 tiles of 32). 4 warps, warp w: e in [w*16, w*16+16).
#define SROW 72   // halves per smem row (144B = 9*16B, conflict-free trans ldsm)
#define STILES 8  // 256 rows / 32
__global__ void __launch_bounds__(128)
s_partial_kernel()
{
    const int bh = blockIdx.x;
    const int j  = blockIdx.y;
    const int b = bh >> 3;
    const int h = bh & 7;

    __shared__ __half Kt[2][32][SROW];
    __shared__ __half Vt[2][32][SROW];

    const int tid = threadIdx.x;
    const int wid = tid >> 5;
    const int lane = tid & 31;
    const int g = lane >> 2;
    const int tg = lane & 3;
    const int e0 = wid * 16;

    const int aRow = ((lane >> 4) & 1) * 8 + (lane & 7);
    const int aCol = e0 + ((lane >> 3) & 1) * 8;
    const int bRow = ((lane >> 3) & 1) * 8 + (lane & 7);
    const int bColOff = ((lane >> 4) & 1) * 8;

    uint32_t kb[2] = { smem_u32(Kt[0]), smem_u32(Kt[1]) };
    uint32_t vb[2] = { smem_u32(Vt[0]), smem_u32(Vt[1]) };

    const size_t koff = 512 + (size_t)h * DH;
    const size_t voff = 1024 + (size_t)h * DH;

    const int cRow0 = tid >> 3;
    const int cSeg  = tid & 7;
    const uint32_t cOff0 = (uint32_t)(cRow0 * SROW + cSeg * 8) * 2;
    const uint32_t cOff1 = (uint32_t)((cRow0 + 16) * SROW + cSeg * 8) * 2;

    float acc[8][4];
#pragma unroll
    for (int ni = 0; ni < 8; ni++)
#pragma unroll
        for (int r = 0; r < 4; r++) acc[ni][r] = 0.f;

    {
        const int g0 = j * (STILES * 32);
        const int s = g0 >> 11;
        const int br = (s * 4 + b) * 2048 + (g0 & 2047);
        size_t r0off = (size_t)(br + cRow0) * QKVN;
        size_t r1off = (size_t)(br + cRow0 + 16) * QKVN;
        cp16(kb[0] + cOff0, &g_QKVh[r0off + koff + cSeg * 8]);
        cp16(kb[0] + cOff1, &g_QKVh[r1off + koff + cSeg * 8]);
        cp16(vb[0] + cOff0, &g_QKVh[r0off + voff + cSeg * 8]);
        cp16(vb[0] + cOff1, &g_QKVh[r1off + voff + cSeg * 8]);
        asm volatile("cp.async.commit_group;" ::: "memory");
    }

    for (int t = 0; t < STILES; ++t) {
        if (t + 1 < STILES) {
            int buf = (t + 1) & 1;
            const int g0 = j * (STILES * 32) + (t + 1) * 32;
            const int s = g0 >> 11;
            const int br = (s * 4 + b) * 2048 + (g0 & 2047);
            size_t r0off = (size_t)(br + cRow0) * QKVN;
            size_t r1off = (size_t)(br + cRow0 + 16) * QKVN;
            cp16(kb[buf] + cOff0, &g_QKVh[r0off + koff + cSeg * 8]);
            cp16(kb[buf] + cOff1, &g_QKVh[r1off + koff + cSeg * 8]);
            cp16(vb[buf] + cOff0, &g_QKVh[r0off + voff + cSeg * 8]);
            cp16(vb[buf] + cOff1, &g_QKVh[r1off + voff + cSeg * 8]);
            asm volatile("cp.async.commit_group;" ::: "memory");
            asm volatile("cp.async.wait_group 1;" ::: "memory");
        } else {
            asm volatile("cp.async.commit_group;" ::: "memory");
            asm volatile("cp.async.wait_group 0;" ::: "memory");
        }
        __syncthreads();

        const int cur = t & 1;
        const uint32_t aAddr0 = kb[cur] + (uint32_t)(aRow * SROW + aCol) * 2;
        const uint32_t bAddr0 = vb[cur] + (uint32_t)(bRow * SROW + bColOff) * 2;
#pragma unroll
        for (int ks = 0; ks < 2; ks++) {
            const uint32_t lOff = (uint32_t)(ks * 16 * SROW) * 2;
            uint32_t a[4];
            ldsm4t(a[0], a[1], a[2], a[3], aAddr0 + lOff);
            uint32_t vB[4][4];
#pragma unroll
            for (int n2 = 0; n2 < 4; n2++)
                ldsm4t(vB[n2][0], vB[n2][1], vB[n2][2], vB[n2][3],
                       bAddr0 + lOff + (uint32_t)(n2 * 16) * 2);
#pragma unroll
            for (int ni = 0; ni < 8; ni++) {
                const uint32_t b0 = (ni & 1) ? vB[ni >> 1][2] : vB[ni >> 1][0];
                const uint32_t b1 = (ni & 1) ? vB[ni >> 1][3] : vB[ni >> 1][1];
                mma_f16(acc[ni][0], acc[ni][1], acc[ni][2], acc[ni][3],
                        a[0], a[1], a[2], a[3], b0, b1);
            }
        }
        __syncthreads();
    }

    float* Sp = &g_Spart[((size_t)j * 32 + bh) * (DH * DH)];
#pragma unroll
    for (int ni = 0; ni < 8; ni++) {
        int col = (ni >> 1) * 16 + (ni & 1) * 8 + 2 * tg;
        int e = e0 + g;
        *reinterpret_cast<float2*>(&Sp[e * DH + col]) = make_float2(acc[ni][0], acc[ni][1]);
        *reinterpret_cast<float2*>(&Sp[(e + 8) * DH + col]) = make_float2(acc[ni][2], acc[ni][3]);
    }
}

// ---------------- S reduce -> transposed fp16 hi/lo (parallelized) -------------
__global__ void __launch_bounds__(128)
s_reduce_kernel()
{
    const int bh = blockIdx.x;
    const int idx4 = blockIdx.y * 128 + threadIdx.x;   // 0..1023
    const size_t base = (size_t)bh * (DH * DH);
    const int e = idx4 >> 4;
    const int d0 = (idx4 & 15) * 4;

    float4 acc = make_float4(0.f, 0.f, 0.f, 0.f);
#pragma unroll
    for (int j = 0; j < NSLICE; j++) {
        float4 v = reinterpret_cast<const float4*>(
            &g_Spart[((size_t)j * 32 + bh) * (DH * DH)])[idx4];
        acc.x += v.x; acc.y += v.y; acc.z += v.z; acc.w += v.w;
    }
    float vals[4] = {acc.x, acc.y, acc.z, acc.w};
#pragma unroll
    for (int k = 0; k < 4; k++) {
        __half hi = __float2half_rn(vals[k]);
        float lo = vals[k] - __half2float(hi);
        g_Shi[base + (size_t)(d0 + k) * DH + e] = hi;
        g_Slo[base + (size_t)(d0 + k) * DH + e] = __float2half_rn(lo);
    }
}

// ---------------- Q @ S (tensor core, split-precision S) ----------------------
__global__ void __launch_bounds__(128)
qs_kernel()
{
    const int h = blockIdx.y;
    const int r0 = blockIdx.x * 128;
    const int b = (r0 >> 11) & 3;

    __shared__ __half Qs[128][SROW];
    __shared__ __half Sh[64][SROW];
    __shared__ __half Sl[64][SROW];

    const int tid = threadIdx.x;
    const int wid = tid >> 5;
    const int lane = tid & 31;
    const int g = lane >> 2;
    const int tg = lane & 3;
    const int m0 = wid * 32;

#pragma unroll
    for (int i = 0; i < 8; i++) {
        int idx = i * 128 + tid;
        int row = idx >> 3, seg = idx & 7;
        *reinterpret_cast<uint4*>(&Qs[row][seg * 8]) =
            *reinterpret_cast<const uint4*>(
                &g_QKVh[(size_t)(r0 + row) * QKVN + (size_t)h * DH + seg * 8]);
    }
    const size_t sbase = (size_t)(b * 8 + h) * (DH * DH);
#pragma unroll
    for (int i = 0; i < 4; i++) {
        int idx = i * 128 + tid;
        int row = idx >> 3, seg = idx & 7;
        *reinterpret_cast<uint4*>(&Sh[row][seg * 8]) =
            *reinterpret_cast<const uint4*>(&g_Shi[sbase + (size_t)row * DH + seg * 8]);
        *reinterpret_cast<uint4*>(&Sl[row][seg * 8]) =
            *reinterpret_cast<const uint4*>(&g_Slo[sbase + (size_t)row * DH + seg * 8]);
    }
    __syncthreads();

    const int rowA = ((lane >> 3) & 1) * 8 + (lane & 7);
    const int cA   = (lane >> 4);
    const int rowB = ((lane >> 4) & 1) * 8 + (lane & 7);
    const int cB   = ((lane >> 3) & 1);

    const uint32_t qb  = smem_u32(Qs);
    const uint32_t shb = smem_u32(Sh);
    const uint32_t slb = smem_u32(Sl);

    float acc[2][8][4];
#pragma unroll
    for (int mi = 0; mi < 2; mi++)
#pragma unroll
        for (int ni = 0; ni < 8; ni++)
#pragma unroll
            for (int r = 0; r < 4; r++) acc[mi][ni][r] = 0.f;

#pragma unroll
    for (int ks = 0; ks < 4; ks++) {
        const uint32_t kByte = (uint32_t)(ks * 32);
        uint32_t a[2][4];
#pragma unroll
        for (int mi = 0; mi < 2; mi++)
            ldsm4(a[mi][0], a[mi][1], a[mi][2], a[mi][3],
                  qb + (uint32_t)((m0 + mi * 16 + rowA) * SROW) * 2 + kByte + cA * 16);
        uint32_t bh_[4][4], bl_[4][4];
#pragma unroll
        for (int n2 = 0; n2 < 4; n2++) {
            uint32_t ro = (uint32_t)((n2 * 16 + rowB) * SROW) * 2 + kByte + cB * 16;
            ldsm4(bh_[n2][0], bh_[n2][1], bh_[n2][2], bh_[n2][3], shb + ro);
            ldsm4(bl_[n2][0], bl_[n2][1], bl_[n2][2], bl_[n2][3], slb + ro);
        }
#pragma unroll
        for (int mi = 0; mi < 2; mi++)
#pragma unroll
            for (int ni = 0; ni < 8; ni++) {
                const uint32_t h0 = (ni & 1) ? bh_[ni >> 1][2] : bh_[ni >> 1][0];
                const uint32_t h1 = (ni & 1) ? bh_[ni >> 1][3] : bh_[ni >> 1][1];
                const uint32_t l0 = (ni & 1) ? bl_[ni >> 1][2] : bl_[ni >> 1][0];
                const uint32_t l1 = (ni & 1) ? bl_[ni >> 1][3] : bl_[ni >> 1][1];
                mma_f16(acc[mi][ni][0], acc[mi][ni][1], acc[mi][ni][2], acc[mi][ni][3],
                        a[mi][0], a[mi][1], a[mi][2], a[mi][3], h0, h1);
                mma_f16(acc[mi][ni][0], acc[mi][ni][1], acc[mi][ni][2], acc[mi][ni][3],
                        a[mi][0], a[mi][1], a[mi][2], a[mi][3], l0, l1);
            }
    }

#pragma unroll
    for (int mi = 0; mi < 2; mi++) {
        int row = r0 + m0 + mi * 16 + g;
#pragma unroll
        for (int ni = 0; ni < 8; ni++) {
            int col = h * DH + (ni >> 1) * 16 + (ni & 1) * 8 + 2 * tg;
            *reinterpret_cast<__half2*>(&g_attnh[(size_t)row * DIM + col]) =
                __floats2half2_rn(acc[mi][ni][0], acc[mi][ni][1]);
            *reinterpret_cast<__half2*>(&g_attnh[(size_t)(row + 8) * DIM + col]) =
                __floats2half2_rn(acc[mi][ni][2], acc[mi][ni][3]);
        }
    }
}

// ---------------- fused residual + LayerNorm ----------------------------------
__global__ void __launch_bounds__(128)
ln_kernel(const float* __restrict__ inA, const float* __restrict__ inB,
          const float* __restrict__ R,
          const float* __restrict__ gamma, const float* __restrict__ beta,
          float* __restrict__ out, __half* __restrict__ outh, int concat)
{
    const int row = blockIdx.x;
    const int tid = threadIdx.x;
    const int c = tid * 4;
    const size_t off = (size_t)row * DIM + c;

    float4 a;
    if (concat) {
        a = *reinterpret_cast<const float4*>(inA + off);
    } else {
        const float* src = (row < HALF_M) ? inA : inB;
        int rl = row & (HALF_M - 1);
        a = *reinterpret_cast<const float4*>(src + (size_t)rl * DIM + c);
    }
    float4 r = *reinterpret_cast<const float4*>(R + off);
    float v0 = a.x + r.x, v1 = a.y + r.y, v2 = a.z + r.z, v3 = a.w + r.w;

    float s = v0 + v1 + v2 + v3;
    float q = v0 * v0 + v1 * v1 + v2 * v2 + v3 * v3;
#pragma unroll
    for (int o = 16; o > 0; o >>= 1) {
        s += __shfl_xor_sync(0xffffffffu, s, o);
        q += __shfl_xor_sync(0xffffffffu, q, o);
    }
    __shared__ float ss[4], sq[4];
    if ((tid & 31) == 0) { ss[tid >> 5] = s; sq[tid >> 5] = q; }
    __syncthreads();
    s = ss[0] + ss[1] + ss[2] + ss[3];
    q = sq[0] + sq[1] + sq[2] + sq[3];

    const float mean = s * (1.f / DIM);
    const float var = q * (1.f / DIM) - mean * mean;
    const float rstd = rsqrtf(var + LN_EPS);

    float4 gv = *reinterpret_cast<const float4*>(gamma + c);
    float4 bv = *reinterpret_cast<const float4*>(beta + c);
    float4 o;
    o.x = (v0 - mean) * rstd * gv.x + bv.x;
    o.y = (v1 - mean) * rstd * gv.y + bv.y;
    o.z = (v2 - mean) * rstd * gv.z + bv.z;
    o.w = (v3 - mean) * rstd * gv.w + bv.w;

    if (!concat) {
        *reinterpret_cast<float4*>(out + off) = o;
        if (outh) h4store(outh + off, o);
    } else {
        int sdx = row >> 13;
        int rem = row & 8191;
        *reinterpret_cast<float4*>(out + (size_t)rem * 1024 + sdx * 512 + c) = o;
    }
}

// ---------------- launch ------------------------------------------------------
extern "C" void kernel_launch(void* const* d_in, const int* in_sizes, int n_in,
                              void* d_out, int out_size)
{
    (void)in_sizes; (void)n_in; (void)out_size;
    const float* question = (const float*)d_in[0];
    const float* query    = (const float*)d_in[1];
    const float* Wq = (const float*)d_in[2];
    const float* bq = (const float*)d_in[3];
    const float* Wk = (const float*)d_in[4];
    const float* bk = (const float*)d_in[5];
    const float* Wv = (const float*)d_in[6];
    const float* bv = (const float*)d_in[7];
    const float* Wo = (const float*)d_in[8];
    const float* bo = (const float*)d_in[9];
    const float* ln_g = (const float*)d_in[10];
    const float* ln_b = (const float*)d_in[11];
    const float* W1 = (const float*)d_in[12];
    const float* b1 = (const float*)d_in[13];
    const float* W2 = (const float*)d_in[14];
    const float* b2 = (const float*)d_in[15];
    float* out = (float*)d_out;

    float *proj, *x1, *ff, *bqkv;
    __half *Xh, *QKVh, *attnh, *x1h, *h1h, *Wqkvh, *Woh, *W1h, *W2h;
    cudaGetSymbolAddress((void**)&Xh,    g_Xh);
    cudaGetSymbolAddress((void**)&QKVh,  g_QKVh);
    cudaGetSymbolAddress((void**)&attnh, g_attnh);
    cudaGetSymbolAddress((void**)&proj,  g_proj);
    cudaGetSymbolAddress((void**)&x1,    g_x1);
    cudaGetSymbolAddress((void**)&x1h,   g_x1h);
    cudaGetSymbolAddress((void**)&h1h,   g_h1h);
    cudaGetSymbolAddress((void**)&ff,    g_ff);
    cudaGetSymbolAddress((void**)&Wqkvh, g_Wqkvh);
    cudaGetSymbolAddress((void**)&bqkv,  g_bqkv);
    cudaGetSymbolAddress((void**)&Woh,   g_Woh);
    cudaGetSymbolAddress((void**)&W1h,   g_W1h);
    cudaGetSymbolAddress((void**)&W2h,   g_W2h);

    const int SMEM_GEMM = NSTAGE * STAGE_BYTES;   // 61440 bytes
    cudaFuncSetAttribute(hgemm_kernel, cudaFuncAttributeMaxDynamicSharedMemorySize, SMEM_GEMM);

    // 0. fused prep + pack (one launch)
    const int PREP_TOTAL = PACK_N4 + 786816;
    prep_pack_kernel<<<(PREP_TOTAL + 255) / 256, 256>>>(
        question, query, Wq, Wk, Wv, Wo, W1, W2, bq, bk, bv);

    // 1. fused QKV projection: [16384 x 1536], fp16 out
    hgemm_kernel<<<dim3(QKVN / 128, MTOT / 128), 128, SMEM_GEMM>>>(
        Xh, Wqkvh, bqkv, QKVh, DIM, QKVN, 0, 1);

    // 2. shared linear-attention state (tensor core + parallel reduce)
    s_partial_kernel<<<dim3(NB * NH, NSLICE), 128>>>();
    s_reduce_kernel<<<dim3(NB * NH, 8), 128>>>();

    // 3. attn = Q @ S (tensor core, split S)
    qs_kernel<<<dim3(MTOT / 128, NH), 128>>>();

    // 4. output projection (fp32 out)
    hgemm_kernel<<<dim3(DIM / 128, MTOT / 128), 128, SMEM_GEMM>>>(
        attnh, Woh, bo, proj, DIM, DIM, 0, 0);

    // 5. LN1: residual read directly from question/query; x1 fp32 + x1h fp16
    ln_kernel<<<MTOT, 128>>>(question, query, proj, ln_g, ln_b, x1, x1h, 0);

    // 6. FF1 (ReLU fused, fp16 out)
    hgemm_kernel<<<dim3(PF / 128, MTOT / 128), 128, SMEM_GEMM>>>(
        x1h, W1h, b1, h1h, DIM, PF, 1, 1);

    // 7. FF2 (fp32 out)
    hgemm_kernel<<<dim3(DIM / 128, MTOT / 128), 128, SMEM_GEMM>>>(
        h1h, W2h, b2, ff, PF, DIM, 0, 0);

    // 8. LN2 + residual + concat
    ln_kernel<<<MTOT, 128>>>(x1, nullptr, ff, ln_g, ln_b, out, nullptr, 1);
}

// round 17
// speedup vs baseline: 1.0622x; 1.0058x over previous
#include <cuda_runtime.h>
#include <cuda_fp16.h>
#include <cstdint>

// Problem constants
#define MTOT 16384      // 2 streams * B(4) * L(2048)
#define HALF_M 8192
#define DIM 512
#define PF 2048
#define QKVN 1536
#define NB 4
#define NH 8
#define DH 64
#define LN_EPS 1e-5f
#define NSLICE 16

// ---------------- scratch (static device globals; no allocation) -------------
__device__ __half g_Xh   [MTOT * DIM];    // fp16 stacked input (GEMM operand)
__device__ __half g_QKVh [MTOT * QKVN];   // fused QKV output (fp16) [Q|K|V]
__device__ __half g_attnh[MTOT * DIM];    // fp16 attn (Wo operand)
__device__ __half g_projh[MTOT * DIM];    // fp16 Wo output (LN1 residual addend)
__device__ float  g_x1   [MTOT * DIM];    // exact (LN2 residual)
__device__ __half g_x1h  [MTOT * DIM];    // fp16 (FF1 operand)
__device__ __half g_h1h  [MTOT * PF];     // fp16 FF intermediate
__device__ __half g_ffh  [MTOT * DIM];    // fp16 FF2 output (LN2 residual addend)
__device__ float  g_Spart[NSLICE * NB * NH * DH * DH];
__device__ __half g_Shi  [NB * NH * DH * DH];   // S^T hi (fp16), layout [bh][d][e]
__device__ __half g_Slo  [NB * NH * DH * DH];   // S^T lo residual (fp16)
// packed fp16 weights + fp32 bias
__device__ __half g_Wqkvh[QKVN * DIM];
__device__ float  g_bqkv [QKVN];
__device__ __half g_Woh  [DIM * DIM];
__device__ __half g_W1h  [PF * DIM];
__device__ __half g_W2h  [DIM * PF];

// ---------------- helpers ----------------------------------------------------
__device__ __forceinline__ uint32_t smem_u32(const void* p) {
    uint32_t a;
    asm("{ .reg .u64 t; cvta.to.shared.u64 t, %1; cvt.u32.u64 %0, t; }" : "=r"(a) : "l"(p));
    return a;
}
__device__ __forceinline__ void mma_f16(float& c0, float& c1, float& c2, float& c3,
                                        uint32_t a0, uint32_t a1, uint32_t a2, uint32_t a3,
                                        uint32_t b0, uint32_t b1)
{
    asm volatile(
        "mma.sync.aligned.m16n8k16.row.col.f32.f16.f16.f32 "
        "{%0,%1,%2,%3}, {%4,%5,%6,%7}, {%8,%9}, {%0,%1,%2,%3};"
        : "+f"(c0), "+f"(c1), "+f"(c2), "+f"(c3)
        : "r"(a0), "r"(a1), "r"(a2), "r"(a3), "r"(b0), "r"(b1));
}
__device__ __forceinline__ void ldsm4(uint32_t& r0, uint32_t& r1, uint32_t& r2, uint32_t& r3,
                                      uint32_t addr)
{
    asm volatile("ldmatrix.sync.aligned.m8n8.x4.shared.b16 {%0,%1,%2,%3}, [%4];"
                 : "=r"(r0), "=r"(r1), "=r"(r2), "=r"(r3) : "r"(addr));
}
__device__ __forceinline__ void ldsm4t(uint32_t& r0, uint32_t& r1, uint32_t& r2, uint32_t& r3,
                                       uint32_t addr)
{
    asm volatile("ldmatrix.sync.aligned.m8n8.x4.trans.shared.b16 {%0,%1,%2,%3}, [%4];"
                 : "=r"(r0), "=r"(r1), "=r"(r2), "=r"(r3) : "r"(addr));
}
__device__ __forceinline__ void cp16(uint32_t saddr, const void* g) {
    asm volatile("cp.async.cg.shared.global [%0], [%1], 16;" :: "r"(saddr), "l"(g) : "memory");
}
__device__ __forceinline__ void h4store(__half* dst, float4 v) {
    __half2* d = reinterpret_cast<__half2*>(dst);
    d[0] = __floats2half2_rn(v.x, v.y);
    d[1] = __floats2half2_rn(v.z, v.w);
}
__device__ __forceinline__ float4 h4load(const __half* src) {
    uint2 raw = *reinterpret_cast<const uint2*>(src);
    const __half2* h = reinterpret_cast<const __half2*>(&raw);
    float2 f0 = __half22float2(h[0]);
    float2 f1 = __half22float2(h[1]);
    return make_float4(f0.x, f0.y, f1.x, f1.y);
}

// ---------------- fused prep + pack (one launch) -------------------------------
#define PACK_N4 (HALF_M * DIM / 4)   // 1048576
__global__ void prep_pack_kernel(const float* __restrict__ qa, const float* __restrict__ qb,
                                 const float* __restrict__ Wq, const float* __restrict__ Wk,
                                 const float* __restrict__ Wv, const float* __restrict__ Wo,
                                 const float* __restrict__ W1, const float* __restrict__ W2,
                                 const float* __restrict__ bq, const float* __restrict__ bk,
                                 const float* __restrict__ bv)
{
    int i = blockIdx.x * blockDim.x + threadIdx.x;
    if (i < PACK_N4) {
        h4store(&g_Xh[(size_t)i * 4],             reinterpret_cast<const float4*>(qa)[i]);
        h4store(&g_Xh[(size_t)(i + PACK_N4) * 4], reinterpret_cast<const float4*>(qb)[i]);
        return;
    }
    int k = i - PACK_N4;
    if (k < 196608) {
        int which = k >> 16, off = k & 65535;
        const float4* src = reinterpret_cast<const float4*>(which == 0 ? Wq : (which == 1 ? Wk : Wv));
        h4store(&g_Wqkvh[(size_t)k * 4], src[off]);
    } else if (k < 262144) {
        int j = k - 196608;
        h4store(&g_Woh[(size_t)j * 4], reinterpret_cast<const float4*>(Wo)[j]);
    } else if (k < 524288) {
        int j = k - 262144;
        h4store(&g_W1h[(size_t)j * 4], reinterpret_cast<const float4*>(W1)[j]);
    } else if (k < 786432) {
        int j = k - 524288;
        h4store(&g_W2h[(size_t)j * 4], reinterpret_cast<const float4*>(W2)[j]);
    } else if (k < 786816) {
        int j = k - 786432;
        const float4* src = reinterpret_cast<const float4*>(j < 128 ? bq : (j < 256 ? bk : bv));
        reinterpret_cast<float4*>(g_bqkv)[j] = src[j & 127];
    }
}

// ============ fp16 mma.sync GEMM (cp.async 3-stage, padded-row smem) ==========
// C[M,N] = A[M,K] @ W[N,K]^T + bias (fp32 accum). 128x128 CTA tile, BK=32,
// 128 threads (4 warps, 2x2), warp tile 64x64.
#define ROWB 80
#define OPER_BYTES (128 * ROWB)      // 10240
#define STAGE_BYTES (2 * OPER_BYTES) // 20480
#define NSTAGE 3

__global__ void __launch_bounds__(128, 2)
hgemm_kernel(const __half* __restrict__ A, const __half* __restrict__ W,
             const float* __restrict__ bias, void* __restrict__ Cv,
             int K, int N, int relu, int outHalf)
{
    extern __shared__ char smem[];

    const int tid  = threadIdx.x;
    const int wid  = tid >> 5;
    const int lane = tid & 31;
    const int g    = lane >> 2;
    const int tg   = lane & 3;
    const int wm   = wid >> 1;
    const int wn   = wid & 1;
    const int bm = blockIdx.y, bn = blockIdx.x;

    const __half* Ag = A + (size_t)bm * 128 * K;
    const __half* Wg = W + (size_t)bn * 128 * K;

    const uint32_t sb = smem_u32(smem);

    uint32_t stOff[4];
    size_t   gOff[4];
#pragma unroll
    for (int i = 0; i < 4; i++) {
        int idx = i * 128 + tid;
        int row = idx >> 2, seg = idx & 3;
        stOff[i] = (uint32_t)(row * ROWB + seg * 16);
        gOff[i]  = (size_t)row * K + seg * 8;
    }

    const int rowA = ((lane >> 3) & 1) * 8 + (lane & 7);
    const int cA   = (lane >> 4);
    const int rowB = ((lane >> 4) & 1) * 8 + (lane & 7);
    const int cB   = ((lane >> 3) & 1);

    uint32_t aRowOff[4], bRowOff[4];
#pragma unroll
    for (int mi = 0; mi < 4; mi++)
        aRowOff[mi] = (uint32_t)((wm * 64 + mi * 16 + rowA) * ROWB);
#pragma unroll
    for (int n2 = 0; n2 < 4; n2++)
        bRowOff[n2] = (uint32_t)(OPER_BYTES + (wn * 64 + n2 * 16 + rowB) * ROWB);

    float acc[4][8][4];
#pragma unroll
    for (int mi = 0; mi < 4; mi++)
#pragma unroll
        for (int ni = 0; ni < 8; ni++)
#pragma unroll
            for (int r = 0; r < 4; r++) acc[mi][ni][r] = 0.f;

    const int NC = K >> 5;

#pragma unroll
    for (int p = 0; p < 2; p++) {
        uint32_t st = sb + p * STAGE_BYTES;
        size_t go = (size_t)p * 32;
#pragma unroll
        for (int i = 0; i < 4; i++) {
            cp16(st + stOff[i],              Ag + gOff[i] + go);
            cp16(st + OPER_BYTES + stOff[i], Wg + gOff[i] + go);
        }
        asm volatile("cp.async.commit_group;" ::: "memory");
    }

    for (int c = 0; c < NC; ++c) {
        asm volatile("cp.async.wait_group 1;" ::: "memory");
        __syncthreads();

        if (c + 2 < NC) {
            int s2 = (c + 2) % NSTAGE;
            uint32_t st = sb + s2 * STAGE_BYTES;
            size_t go = (size_t)(c + 2) * 32;
#pragma unroll
            for (int i = 0; i < 4; i++) {
                cp16(st + stOff[i],              Ag + gOff[i] + go);
                cp16(st + OPER_BYTES + stOff[i], Wg + gOff[i] + go);
            }
        }
        asm volatile("cp.async.commit_group;" ::: "memory");

        const uint32_t base = sb + (c % NSTAGE) * STAGE_BYTES;
#pragma unroll
        for (int ks = 0; ks < 2; ks++) {
            uint32_t a[4][4];
#pragma unroll
            for (int mi = 0; mi < 4; mi++)
                ldsm4(a[mi][0], a[mi][1], a[mi][2], a[mi][3],
                      base + aRowOff[mi] + (uint32_t)((ks * 2 + cA) * 16));
            uint32_t b[4][4];
#pragma unroll
            for (int n2 = 0; n2 < 4; n2++)
                ldsm4(b[n2][0], b[n2][1], b[n2][2], b[n2][3],
                      base + bRowOff[n2] + (uint32_t)((ks * 2 + cB) * 16));
#pragma unroll
            for (int mi = 0; mi < 4; mi++)
#pragma unroll
                for (int ni = 0; ni < 8; ni++) {
                    const uint32_t b0 = (ni & 1) ? b[ni >> 1][2] : b[ni >> 1][0];
                    const uint32_t b1 = (ni & 1) ? b[ni >> 1][3] : b[ni >> 1][1];
                    mma_f16(acc[mi][ni][0], acc[mi][ni][1], acc[mi][ni][2], acc[mi][ni][3],
                            a[mi][0], a[mi][1], a[mi][2], a[mi][3], b0, b1);
                }
        }
    }

    const float2* bias2 = reinterpret_cast<const float2*>(bias);
#pragma unroll
    for (int mi = 0; mi < 4; mi++) {
        int r0 = bm * 128 + wm * 64 + mi * 16 + g;
#pragma unroll
        for (int ni = 0; ni < 8; ni++) {
            int col = bn * 128 + wn * 64 + ni * 8 + 2 * tg;
            float2 bv = __ldg(&bias2[col >> 1]);
            float2 o0, o1;
            o0.x = acc[mi][ni][0] + bv.x;
            o0.y = acc[mi][ni][1] + bv.y;
            o1.x = acc[mi][ni][2] + bv.x;
            o1.y = acc[mi][ni][3] + bv.y;
            if (relu) {
                o0.x = fmaxf(o0.x, 0.f); o0.y = fmaxf(o0.y, 0.f);
                o1.x = fmaxf(o1.x, 0.f); o1.y = fmaxf(o1.y, 0.f);
            }
            if (outHalf) {
                __half* C = (__half*)Cv;
                *reinterpret_cast<__half2*>(C + (size_t)r0 * N + col) =
                    __floats2half2_rn(o0.x, o0.y);
                *reinterpret_cast<__half2*>(C + (size_t)(r0 + 8) * N + col) =
                    __floats2half2_rn(o1.x, o1.y);
            } else {
                float* C = (float*)Cv;
                *reinterpret_cast<float2*>(C + (size_t)r0 * N + col) = o0;
                *reinterpret_cast<float2*>(C + (size_t)(r0 + 8) * N + col) = o1;
            }
        }
    }
}

// ---------------- S partial (tensor core, cp.async double-buffered) -----------
// Each CTA: 256 rows (8 tiles of 32). 4 warps, warp w: e in [w*16, w*16+16).
#define SROW 72   // halves per smem row (144B = 9*16B, conflict-free trans ldsm)
#define STILES 8  // 256 rows / 32
__global__ void __launch_bounds__(128)
s_partial_kernel()
{
    const int bh = blockIdx.x;
    const int j  = blockIdx.y;
    const int b = bh >> 3;
    const int h = bh & 7;

    __shared__ __half Kt[2][32][SROW];
    __shared__ __half Vt[2][32][SROW];

    const int tid = threadIdx.x;
    const int wid = tid >> 5;
    const int lane = tid & 31;
    const int g = lane >> 2;
    const int tg = lane & 3;
    const int e0 = wid * 16;

    const int aRow = ((lane >> 4) & 1) * 8 + (lane & 7);
    const int aCol = e0 + ((lane >> 3) & 1) * 8;
    const int bRow = ((lane >> 3) & 1) * 8 + (lane & 7);
    const int bColOff = ((lane >> 4) & 1) * 8;

    uint32_t kb[2] = { smem_u32(Kt[0]), smem_u32(Kt[1]) };
    uint32_t vb[2] = { smem_u32(Vt[0]), smem_u32(Vt[1]) };

    const size_t koff = 512 + (size_t)h * DH;
    const size_t voff = 1024 + (size_t)h * DH;

    const int cRow0 = tid >> 3;
    const int cSeg  = tid & 7;
    const uint32_t cOff0 = (uint32_t)(cRow0 * SROW + cSeg * 8) * 2;
    const uint32_t cOff1 = (uint32_t)((cRow0 + 16) * SROW + cSeg * 8) * 2;

    float acc[8][4];
#pragma unroll
    for (int ni = 0; ni < 8; ni++)
#pragma unroll
        for (int r = 0; r < 4; r++) acc[ni][r] = 0.f;

    {
        const int g0 = j * (STILES * 32);
        const int s = g0 >> 11;
        const int br = (s * 4 + b) * 2048 + (g0 & 2047);
        size_t r0off = (size_t)(br + cRow0) * QKVN;
        size_t r1off = (size_t)(br + cRow0 + 16) * QKVN;
        cp16(kb[0] + cOff0, &g_QKVh[r0off + koff + cSeg * 8]);
        cp16(kb[0] + cOff1, &g_QKVh[r1off + koff + cSeg * 8]);
        cp16(vb[0] + cOff0, &g_QKVh[r0off + voff + cSeg * 8]);
        cp16(vb[0] + cOff1, &g_QKVh[r1off + voff + cSeg * 8]);
        asm volatile("cp.async.commit_group;" ::: "memory");
    }

    for (int t = 0; t < STILES; ++t) {
        if (t + 1 < STILES) {
            int buf = (t + 1) & 1;
            const int g0 = j * (STILES * 32) + (t + 1) * 32;
            const int s = g0 >> 11;
            const int br = (s * 4 + b) * 2048 + (g0 & 2047);
            size_t r0off = (size_t)(br + cRow0) * QKVN;
            size_t r1off = (size_t)(br + cRow0 + 16) * QKVN;
            cp16(kb[buf] + cOff0, &g_QKVh[r0off + koff + cSeg * 8]);
            cp16(kb[buf] + cOff1, &g_QKVh[r1off + koff + cSeg * 8]);
            cp16(vb[buf] + cOff0, &g_QKVh[r0off + voff + cSeg * 8]);
            cp16(vb[buf] + cOff1, &g_QKVh[r1off + voff + cSeg * 8]);
            asm volatile("cp.async.commit_group;" ::: "memory");
            asm volatile("cp.async.wait_group 1;" ::: "memory");
        } else {
            asm volatile("cp.async.commit_group;" ::: "memory");
            asm volatile("cp.async.wait_group 0;" ::: "memory");
        }
        __syncthreads();

        const int cur = t & 1;
        const uint32_t aAddr0 = kb[cur] + (uint32_t)(aRow * SROW + aCol) * 2;
        const uint32_t bAddr0 = vb[cur] + (uint32_t)(bRow * SROW + bColOff) * 2;
#pragma unroll
        for (int ks = 0; ks < 2; ks++) {
            const uint32_t lOff = (uint32_t)(ks * 16 * SROW) * 2;
            uint32_t a[4];
            ldsm4t(a[0], a[1], a[2], a[3], aAddr0 + lOff);
            uint32_t vB[4][4];
#pragma unroll
            for (int n2 = 0; n2 < 4; n2++)
                ldsm4t(vB[n2][0], vB[n2][1], vB[n2][2], vB[n2][3],
                       bAddr0 + lOff + (uint32_t)(n2 * 16) * 2);
#pragma unroll
            for (int ni = 0; ni < 8; ni++) {
                const uint32_t b0 = (ni & 1) ? vB[ni >> 1][2] : vB[ni >> 1][0];
                const uint32_t b1 = (ni & 1) ? vB[ni >> 1][3] : vB[ni >> 1][1];
                mma_f16(acc[ni][0], acc[ni][1], acc[ni][2], acc[ni][3],
                        a[0], a[1], a[2], a[3], b0, b1);
            }
        }
        __syncthreads();
    }

    float* Sp = &g_Spart[((size_t)j * 32 + bh) * (DH * DH)];
#pragma unroll
    for (int ni = 0; ni < 8; ni++) {
        int col = (ni >> 1) * 16 + (ni & 1) * 8 + 2 * tg;
        int e = e0 + g;
        *reinterpret_cast<float2*>(&Sp[e * DH + col]) = make_float2(acc[ni][0], acc[ni][1]);
        *reinterpret_cast<float2*>(&Sp[(e + 8) * DH + col]) = make_float2(acc[ni][2], acc[ni][3]);
    }
}

// ---------------- S reduce -> transposed fp16 hi/lo (parallelized) -------------
__global__ void __launch_bounds__(128)
s_reduce_kernel()
{
    const int bh = blockIdx.x;
    const int idx4 = blockIdx.y * 128 + threadIdx.x;   // 0..1023
    const size_t base = (size_t)bh * (DH * DH);
    const int e = idx4 >> 4;
    const int d0 = (idx4 & 15) * 4;

    float4 acc = make_float4(0.f, 0.f, 0.f, 0.f);
#pragma unroll
    for (int j = 0; j < NSLICE; j++) {
        float4 v = reinterpret_cast<const float4*>(
            &g_Spart[((size_t)j * 32 + bh) * (DH * DH)])[idx4];
        acc.x += v.x; acc.y += v.y; acc.z += v.z; acc.w += v.w;
    }
    float vals[4] = {acc.x, acc.y, acc.z, acc.w};
#pragma unroll
    for (int k = 0; k < 4; k++) {
        __half hi = __float2half_rn(vals[k]);
        float lo = vals[k] - __half2float(hi);
        g_Shi[base + (size_t)(d0 + k) * DH + e] = hi;
        g_Slo[base + (size_t)(d0 + k) * DH + e] = __float2half_rn(lo);
    }
}

// ---------------- Q @ S (tensor core, split-precision S) ----------------------
__global__ void __launch_bounds__(128)
qs_kernel()
{
    const int h = blockIdx.y;
    const int r0 = blockIdx.x * 128;
    const int b = (r0 >> 11) & 3;

    __shared__ __half Qs[128][SROW];
    __shared__ __half Sh[64][SROW];
    __shared__ __half Sl[64][SROW];

    const int tid = threadIdx.x;
    const int wid = tid >> 5;
    const int lane = tid & 31;
    const int g = lane >> 2;
    const int tg = lane & 3;
    const int m0 = wid * 32;

#pragma unroll
    for (int i = 0; i < 8; i++) {
        int idx = i * 128 + tid;
        int row = idx >> 3, seg = idx & 7;
        *reinterpret_cast<uint4*>(&Qs[row][seg * 8]) =
            *reinterpret_cast<const uint4*>(
                &g_QKVh[(size_t)(r0 + row) * QKVN + (size_t)h * DH + seg * 8]);
    }
    const size_t sbase = (size_t)(b * 8 + h) * (DH * DH);
#pragma unroll
    for (int i = 0; i < 4; i++) {
        int idx = i * 128 + tid;
        int row = idx >> 3, seg = idx & 7;
        *reinterpret_cast<uint4*>(&Sh[row][seg * 8]) =
            *reinterpret_cast<const uint4*>(&g_Shi[sbase + (size_t)row * DH + seg * 8]);
        *reinterpret_cast<uint4*>(&Sl[row][seg * 8]) =
            *reinterpret_cast<const uint4*>(&g_Slo[sbase + (size_t)row * DH + seg * 8]);
    }
    __syncthreads();

    const int rowA = ((lane >> 3) & 1) * 8 + (lane & 7);
    const int cA   = (lane >> 4);
    const int rowB = ((lane >> 4) & 1) * 8 + (lane & 7);
    const int cB   = ((lane >> 3) & 1);

    const uint32_t qb  = smem_u32(Qs);
    const uint32_t shb = smem_u32(Sh);
    const uint32_t slb = smem_u32(Sl);

    float acc[2][8][4];
#pragma unroll
    for (int mi = 0; mi < 2; mi++)
#pragma unroll
        for (int ni = 0; ni < 8; ni++)
#pragma unroll
            for (int r = 0; r < 4; r++) acc[mi][ni][r] = 0.f;

#pragma unroll
    for (int ks = 0; ks < 4; ks++) {
        const uint32_t kByte = (uint32_t)(ks * 32);
        uint32_t a[2][4];
#pragma unroll
        for (int mi = 0; mi < 2; mi++)
            ldsm4(a[mi][0], a[mi][1], a[mi][2], a[mi][3],
                  qb + (uint32_t)((m0 + mi * 16 + rowA) * SROW) * 2 + kByte + cA * 16);
        uint32_t bh_[4][4], bl_[4][4];
#pragma unroll
        for (int n2 = 0; n2 < 4; n2++) {
            uint32_t ro = (uint32_t)((n2 * 16 + rowB) * SROW) * 2 + kByte + cB * 16;
            ldsm4(bh_[n2][0], bh_[n2][1], bh_[n2][2], bh_[n2][3], shb + ro);
            ldsm4(bl_[n2][0], bl_[n2][1], bl_[n2][2], bl_[n2][3], slb + ro);
        }
#pragma unroll
        for (int mi = 0; mi < 2; mi++)
#pragma unroll
            for (int ni = 0; ni < 8; ni++) {
                const uint32_t h0 = (ni & 1) ? bh_[ni >> 1][2] : bh_[ni >> 1][0];
                const uint32_t h1 = (ni & 1) ? bh_[ni >> 1][3] : bh_[ni >> 1][1];
                const uint32_t l0 = (ni & 1) ? bl_[ni >> 1][2] : bl_[ni >> 1][0];
                const uint32_t l1 = (ni & 1) ? bl_[ni >> 1][3] : bl_[ni >> 1][1];
                mma_f16(acc[mi][ni][0], acc[mi][ni][1], acc[mi][ni][2], acc[mi][ni][3],
                        a[mi][0], a[mi][1], a[mi][2], a[mi][3], h0, h1);
                mma_f16(acc[mi][ni][0], acc[mi][ni][1], acc[mi][ni][2], acc[mi][ni][3],
                        a[mi][0], a[mi][1], a[mi][2], a[mi][3], l0, l1);
            }
    }

#pragma unroll
    for (int mi = 0; mi < 2; mi++) {
        int row = r0 + m0 + mi * 16 + g;
#pragma unroll
        for (int ni = 0; ni < 8; ni++) {
            int col = h * DH + (ni >> 1) * 16 + (ni & 1) * 8 + 2 * tg;
            *reinterpret_cast<__half2*>(&g_attnh[(size_t)row * DIM + col]) =
                __floats2half2_rn(acc[mi][ni][0], acc[mi][ni][1]);
            *reinterpret_cast<__half2*>(&g_attnh[(size_t)(row + 8) * DIM + col]) =
                __floats2half2_rn(acc[mi][ni][2], acc[mi][ni][3]);
        }
    }
}

// ---------------- fused residual + LayerNorm (fp16 residual addend R) ---------
__global__ void __launch_bounds__(128)
ln_kernel(const float* __restrict__ inA, const float* __restrict__ inB,
          const __half* __restrict__ R,
          const float* __restrict__ gamma, const float* __restrict__ beta,
          float* __restrict__ out, __half* __restrict__ outh, int concat)
{
    const int row = blockIdx.x;
    const int tid = threadIdx.x;
    const int c = tid * 4;
    const size_t off = (size_t)row * DIM + c;

    float4 a;
    if (concat) {
        a = *reinterpret_cast<const float4*>(inA + off);
    } else {
        const float* src = (row < HALF_M) ? inA : inB;
        int rl = row & (HALF_M - 1);
        a = *reinterpret_cast<const float4*>(src + (size_t)rl * DIM + c);
    }
    float4 r = h4load(R + off);
    float v0 = a.x + r.x, v1 = a.y + r.y, v2 = a.z + r.z, v3 = a.w + r.w;

    float s = v0 + v1 + v2 + v3;
    float q = v0 * v0 + v1 * v1 + v2 * v2 + v3 * v3;
#pragma unroll
    for (int o = 16; o > 0; o >>= 1) {
        s += __shfl_xor_sync(0xffffffffu, s, o);
        q += __shfl_xor_sync(0xffffffffu, q, o);
    }
    __shared__ float ss[4], sq[4];
    if ((tid & 31) == 0) { ss[tid >> 5] = s; sq[tid >> 5] = q; }
    __syncthreads();
    s = ss[0] + ss[1] + ss[2] + ss[3];
    q = sq[0] + sq[1] + sq[2] + sq[3];

    const float mean = s * (1.f / DIM);
    const float var = q * (1.f / DIM) - mean * mean;
    const float rstd = rsqrtf(var + LN_EPS);

    float4 gv = *reinterpret_cast<const float4*>(gamma + c);
    float4 bv = *reinterpret_cast<const float4*>(beta + c);
    float4 o;
    o.x = (v0 - mean) * rstd * gv.x + bv.x;
    o.y = (v1 - mean) * rstd * gv.y + bv.y;
    o.z = (v2 - mean) * rstd * gv.z + bv.z;
    o.w = (v3 - mean) * rstd * gv.w + bv.w;

    if (!concat) {
        *reinterpret_cast<float4*>(out + off) = o;
        if (outh) h4store(outh + off, o);
    } else {
        int sdx = row >> 13;
        int rem = row & 8191;
        *reinterpret_cast<float4*>(out + (size_t)rem * 1024 + sdx * 512 + c) = o;
    }
}

// ---------------- launch ------------------------------------------------------
extern "C" void kernel_launch(void* const* d_in, const int* in_sizes, int n_in,
                              void* d_out, int out_size)
{
    (void)in_sizes; (void)n_in; (void)out_size;
    const float* question = (const float*)d_in[0];
    const float* query    = (const float*)d_in[1];
    const float* Wq = (const float*)d_in[2];
    const float* bq = (const float*)d_in[3];
    const float* Wk = (const float*)d_in[4];
    const float* bk = (const float*)d_in[5];
    const float* Wv = (const float*)d_in[6];
    const float* bv = (const float*)d_in[7];
    const float* Wo = (const float*)d_in[8];
    const float* bo = (const float*)d_in[9];
    const float* ln_g = (const float*)d_in[10];
    const float* ln_b = (const float*)d_in[11];
    const float* W1 = (const float*)d_in[12];
    const float* b1 = (const float*)d_in[13];
    const float* W2 = (const float*)d_in[14];
    const float* b2 = (const float*)d_in[15];
    float* out = (float*)d_out;

    float *x1, *bqkv;
    __half *Xh, *QKVh, *attnh, *projh, *x1h, *h1h, *ffh, *Wqkvh, *Woh, *W1h, *W2h;
    cudaGetSymbolAddress((void**)&Xh,    g_Xh);
    cudaGetSymbolAddress((void**)&QKVh,  g_QKVh);
    cudaGetSymbolAddress((void**)&attnh, g_attnh);
    cudaGetSymbolAddress((void**)&projh, g_projh);
    cudaGetSymbolAddress((void**)&x1,    g_x1);
    cudaGetSymbolAddress((void**)&x1h,   g_x1h);
    cudaGetSymbolAddress((void**)&h1h,   g_h1h);
    cudaGetSymbolAddress((void**)&ffh,   g_ffh);
    cudaGetSymbolAddress((void**)&Wqkvh, g_Wqkvh);
    cudaGetSymbolAddress((void**)&bqkv,  g_bqkv);
    cudaGetSymbolAddress((void**)&Woh,   g_Woh);
    cudaGetSymbolAddress((void**)&W1h,   g_W1h);
    cudaGetSymbolAddress((void**)&W2h,   g_W2h);

    const int SMEM_GEMM = NSTAGE * STAGE_BYTES;   // 61440 bytes
    cudaFuncSetAttribute(hgemm_kernel, cudaFuncAttributeMaxDynamicSharedMemorySize, SMEM_GEMM);

    // 0. fused prep + pack (one launch)
    const int PREP_TOTAL = PACK_N4 + 786816;
    prep_pack_kernel<<<(PREP_TOTAL + 255) / 256, 256>>>(
        question, query, Wq, Wk, Wv, Wo, W1, W2, bq, bk, bv);

    // 1. fused QKV projection: [16384 x 1536], fp16 out
    hgemm_kernel<<<dim3(QKVN / 128, MTOT / 128), 128, SMEM_GEMM>>>(
        Xh, Wqkvh, bqkv, QKVh, DIM, QKVN, 0, 1);

    // 2. shared linear-attention state (tensor core + parallel reduce)
    s_partial_kernel<<<dim3(NB * NH, NSLICE), 128>>>();
    s_reduce_kernel<<<dim3(NB * NH, 8), 128>>>();

    // 3. attn = Q @ S (tensor core, split S)
    qs_kernel<<<dim3(MTOT / 128, NH), 128>>>();

    // 4. output projection (fp16 out)
    hgemm_kernel<<<dim3(DIM / 128, MTOT / 128), 128, SMEM_GEMM>>>(
        attnh, Woh, bo, projh, DIM, DIM, 0, 1);

    // 5. LN1: residual from question/query + fp16 proj; x1 fp32 + x1h fp16
    ln_kernel<<<MTOT, 128>>>(question, query, projh, ln_g, ln_b, x1, x1h, 0);

    // 6. FF1 (ReLU fused, fp16 out)
    hgemm_kernel<<<dim3(PF / 128, MTOT / 128), 128, SMEM_GEMM>>>(
        x1h, W1h, b1, h1h, DIM, PF, 1, 1);

    // 7. FF2 (fp16 out)
    hgemm_kernel<<<dim3(DIM / 128, MTOT / 128), 128, SMEM_GEMM>>>(
        h1h, W2h, b2, ffh, PF, DIM, 0, 1);

    // 8. LN2 + residual + concat
    ln_kernel<<<MTOT, 128>>>(x1, nullptr, ffh, ln_g, ln_b, out, nullptr, 1);
}